// round 12
// baseline (speedup 1.0000x reference)
#include <cuda_runtime.h>

#define H 1024
#define B 8
#define T 4096
#define NROWS (B * T)

#define GRID   296                 // 148 SMs x 2 blocks — all co-resident
#define NWARPS (GRID * 8)          // 2368 warps, ~14 rows each
#define V_WRITERS 256              // blocks 0..255 compute 4 v-rows each

__device__ float g_v[B * H];
__device__ int   g_cnt;            // writers-done counter (self-resetting)
__device__ int   g_passed;         // blocks-past-spin counter (self-resetting)

__device__ __forceinline__ int ld_acquire(const int* p) {
    int v;
    asm volatile("ld.global.acquire.gpu.b32 %0, [%1];" : "=r"(v) : "l"(p) : "memory");
    return v;
}

__device__ __forceinline__ void load_row(float4 (&x)[8],
                                         const float* __restrict__ states,
                                         int row, int lane)
{
    const float4* s4 = reinterpret_cast<const float4*>(states + (size_t)row * H);
#pragma unroll
    for (int k = 0; k < 8; k++) x[k] = s4[lane + 32 * k];
}

__device__ __forceinline__ void dot_store(const float4 (&x)[8],
                                          int row, int lane, float bb,
                                          float* __restrict__ out)
{
    const float4* v4 = reinterpret_cast<const float4*>(g_v + ((row >> 12) << 10));
    float acc0 = 0.0f, acc1 = 0.0f;
#pragma unroll
    for (int k = 0; k < 8; k += 2) {
        const float4 w0 = __ldg(v4 + lane + 32 * k);
        const float4 w1 = __ldg(v4 + lane + 32 * (k + 1));
        acc0 += x[k].x * w0.x + x[k].y * w0.y + x[k].z * w0.z + x[k].w * w0.w;
        acc1 += x[k+1].x * w1.x + x[k+1].y * w1.y + x[k+1].z * w1.z + x[k+1].w * w1.w;
    }
    float acc = acc0 + acc1;
#pragma unroll
    for (int o = 16; o; o >>= 1)
        acc += __shfl_xor_sync(0xFFFFFFFFu, acc, o);
    if (lane == 0) out[row] = acc + bb;
}

// Fused kernel: v-phase (blocks 0..255) + spin barrier + R10 ping-pong engine.
__global__ void __launch_bounds__(256, 2) fused_kernel(
    const float* __restrict__ states,  // (B, T, H)
    const float* __restrict__ ctx,     // (B, H)
    const float* __restrict__ W,       // (H, H)
    const float* __restrict__ bias,    // (1,)
    float* __restrict__ out)           // (B*T,)
{
    __shared__ float red[4][8][9];

    const int tid  = threadIdx.x;
    const int lane = tid & 31;
    const int warp = tid >> 5;
    const int wg   = blockIdx.x * 8 + warp;

    // Pre-issue this warp's first states row (DRAM) — hides the v-phase.
    float4 xa[8], xb[8];
    const int r0 = wg;
    load_row(xa, states, r0, lane);
    const float bb = bias[0];

    // ── v-phase: blocks 0..255 compute 4 rows of v = W @ ctx ──
    if (blockIdx.x < V_WRITERS) {
#pragma unroll
        for (int r = 0; r < 4; r++) {
            const int row = blockIdx.x * 4 + r;
            const float4 w4 =
                __ldg(reinterpret_cast<const float4*>(W + (size_t)row * H) + tid);
            float acc[B];
#pragma unroll
            for (int b = 0; b < B; b++) {
                const float4 c = __ldg(reinterpret_cast<const float4*>(ctx + b * H) + tid);
                acc[b] = w4.x * c.x + w4.y * c.y + w4.z * c.z + w4.w * c.w;
            }
#pragma unroll
            for (int b = 0; b < B; b++) {
#pragma unroll
                for (int o = 16; o; o >>= 1)
                    acc[b] += __shfl_xor_sync(0xFFFFFFFFu, acc[b], o);
            }
            if (lane == 0) {
#pragma unroll
                for (int b = 0; b < B; b++) red[r][warp][b] = acc[b];
            }
        }
        __syncthreads();
        if (tid < 4 * B) {
            const int r = tid >> 3, b = tid & 7;
            float s = 0.0f;
#pragma unroll
            for (int wi = 0; wi < 8; wi++) s += red[r][wi][b];
            g_v[b * H + blockIdx.x * 4 + r] = s;
        }
        __syncthreads();
        if (tid == 0) {
            __threadfence();                 // publish g_v device-wide
            atomicAdd(&g_cnt, 1);
        }
    }

    // ── spin barrier: wait for all 256 writer blocks ──
    if (tid == 0) {
        while (ld_acquire(&g_cnt) < V_WRITERS) __nanosleep(64);
        // self-reset for next graph replay: last block past the spin zeroes both
        const int old = atomicAdd(&g_passed, 1);
        if (old == GRID - 1) {
            atomicExch(&g_cnt, 0);
            atomicExch(&g_passed, 0);
        }
    }
    __syncthreads();

    // ── R10 engine: register ping-pong over ~14 rows per warp ──
    int ra = r0;
    int rb = ra + NWARPS;
    for (;;) {
        if (rb < NROWS) load_row(xb, states, rb, lane);   // prefetch next
        dot_store(xa, ra, lane, bb, out);                 // consume current
        if (rb >= NROWS) break;

        ra = rb + NWARPS;
        if (ra < NROWS) load_row(xa, states, ra, lane);
        dot_store(xb, rb, lane, bb, out);
        if (ra >= NROWS) break;

        rb = ra + NWARPS;
    }
}

extern "C" void kernel_launch(void* const* d_in, const int* in_sizes, int n_in,
                              void* d_out, int out_size)
{
    const float* states = (const float*)d_in[0];   // (B, T, H)
    const float* ctx    = (const float*)d_in[1];   // (B, H)
    const float* W      = (const float*)d_in[2];   // (1, H, H)
    const float* bias   = (const float*)d_in[3];   // (1,)

    fused_kernel<<<GRID, 256>>>(states, ctx, W, bias, (float*)d_out);
}

// round 13
// speedup vs baseline: 1.1306x; 1.1306x over previous
#include <cuda_runtime.h>

#define H 1024
#define B 8
#define T 4096
#define NROWS (B * T)

#define GRID   296                 // 148 SMs x 2 blocks — all co-resident
#define NWARPS (GRID * 8)          // 2368 warps, ~14 rows each
#define V_WRITERS 256              // blocks 0..255 compute 4 v-rows each

__device__ float g_v[B * H];
__device__ int   g_cnt;            // writers-done counter (self-resetting)
__device__ int   g_passed;         // blocks-past-spin counter (self-resetting)

__device__ __forceinline__ int ld_acquire(const int* p) {
    int v;
    asm volatile("ld.global.acquire.gpu.b32 %0, [%1];" : "=r"(v) : "l"(p) : "memory");
    return v;
}

__device__ __forceinline__ void load_row(float4 (&x)[8],
                                         const float* __restrict__ states,
                                         int row, int lane)
{
    const float4* s4 = reinterpret_cast<const float4*>(states + (size_t)row * H);
#pragma unroll
    for (int k = 0; k < 8; k++) x[k] = s4[lane + 32 * k];
}

__device__ __forceinline__ void dot_store(const float4 (&x)[8],
                                          int row, int lane, float bb,
                                          float* __restrict__ out)
{
    const float4* v4 = reinterpret_cast<const float4*>(g_v + ((row >> 12) << 10));
    float acc0 = 0.0f, acc1 = 0.0f;
#pragma unroll
    for (int k = 0; k < 8; k += 2) {
        const float4 w0 = __ldg(v4 + lane + 32 * k);
        const float4 w1 = __ldg(v4 + lane + 32 * (k + 1));
        acc0 += x[k].x * w0.x + x[k].y * w0.y + x[k].z * w0.z + x[k].w * w0.w;
        acc1 += x[k+1].x * w1.x + x[k+1].y * w1.y + x[k+1].z * w1.z + x[k+1].w * w1.w;
    }
    float acc = acc0 + acc1;
#pragma unroll
    for (int o = 16; o; o >>= 1)
        acc += __shfl_xor_sync(0xFFFFFFFFu, acc, o);
    if (lane == 0) out[row] = acc + bb;
}

// Fused: v-phase (blocks 0..255, NOTHING held live across it) + spin barrier
// + R10 register-ping-pong engine.
__global__ void __launch_bounds__(256, 2) fused_kernel(
    const float* __restrict__ states,  // (B, T, H)
    const float* __restrict__ ctx,     // (B, H)
    const float* __restrict__ W,       // (H, H)
    const float* __restrict__ bias,    // (1,)
    float* __restrict__ out)           // (B*T,)
{
    __shared__ float red[4][8][9];

    const int tid  = threadIdx.x;
    const int lane = tid & 31;
    const int warp = tid >> 5;

    // ── v-phase: blocks 0..255 compute 4 rows of v = W @ ctx ──
    // No engine state is live here, so registers are free for this phase.
    if (blockIdx.x < V_WRITERS) {
#pragma unroll
        for (int r = 0; r < 4; r++) {
            const int row = blockIdx.x * 4 + r;
            const float4 w4 =
                __ldg(reinterpret_cast<const float4*>(W + (size_t)row * H) + tid);
            float acc[B];
#pragma unroll
            for (int b = 0; b < B; b++) {
                const float4 c = __ldg(reinterpret_cast<const float4*>(ctx + b * H) + tid);
                acc[b] = w4.x * c.x + w4.y * c.y + w4.z * c.z + w4.w * c.w;
            }
#pragma unroll
            for (int b = 0; b < B; b++) {
#pragma unroll
                for (int o = 16; o; o >>= 1)
                    acc[b] += __shfl_xor_sync(0xFFFFFFFFu, acc[b], o);
            }
            if (lane == 0) {
#pragma unroll
                for (int b = 0; b < B; b++) red[r][warp][b] = acc[b];
            }
        }
        __syncthreads();
        if (tid < 4 * B) {
            const int r = tid >> 3, b = tid & 7;
            float s = 0.0f;
#pragma unroll
            for (int wi = 0; wi < 8; wi++) s += red[r][wi][b];
            g_v[b * H + blockIdx.x * 4 + r] = s;
        }
        __syncthreads();
        if (tid == 0) {
            __threadfence();                 // publish g_v device-wide
            atomicAdd(&g_cnt, 1);
        }
    }

    // ── spin barrier: wait for all 256 writer blocks; self-reset for replay ──
    if (tid == 0) {
        while (ld_acquire(&g_cnt) < V_WRITERS) __nanosleep(32);
        const int old = atomicAdd(&g_passed, 1);
        if (old == GRID - 1) {
            atomicExch(&g_cnt, 0);
            atomicExch(&g_passed, 0);
        }
    }
    __syncthreads();

    // ── engine: register ping-pong over ~14 rows per warp ──
    const int wg = blockIdx.x * 8 + warp;
    const float bb = bias[0];

    float4 xa[8], xb[8];
    int ra = wg;
    load_row(xa, states, ra, lane);

    int rb = ra + NWARPS;
    for (;;) {
        if (rb < NROWS) load_row(xb, states, rb, lane);   // prefetch next
        dot_store(xa, ra, lane, bb, out);                 // consume current
        if (rb >= NROWS) break;

        ra = rb + NWARPS;
        if (ra < NROWS) load_row(xa, states, ra, lane);
        dot_store(xb, rb, lane, bb, out);
        if (ra >= NROWS) break;

        rb = ra + NWARPS;
    }
}

extern "C" void kernel_launch(void* const* d_in, const int* in_sizes, int n_in,
                              void* d_out, int out_size)
{
    const float* states = (const float*)d_in[0];   // (B, T, H)
    const float* ctx    = (const float*)d_in[1];   // (B, H)
    const float* W      = (const float*)d_in[2];   // (1, H, H)
    const float* bias   = (const float*)d_in[3];   // (1,)

    fused_kernel<<<GRID, 256>>>(states, ctx, W, bias, (float*)d_out);
}